// round 1
// baseline (speedup 1.0000x reference)
#include <cuda_runtime.h>

#define AZI_C 0.006135923151542565f
#define INC_C 0.008267349088394194f

#define NPIX 262144          // total pixels (B*W*H)
#define PPB  65536           // pixels per batch (W*H)

// scratch (alloc-free rule: device globals)
__device__ float g_U[64 * NPIX];     // 64 MB
__device__ float g_V[64 * NPIX];     // 64 MB
__device__ float g_mean[128];
__device__ float g_rstd[128];

// ---------------------------------------------------------------------------
// GroupNorm statistics: one block per (batch, group). Each group's data is
// 131072 contiguous floats (2 channels x 65536 pixels, channels contiguous).
// ---------------------------------------------------------------------------
__global__ void gn_stats_kernel(const float* __restrict__ in) {
    int bg = blockIdx.x;                  // b*32 + g
    int t  = threadIdx.x;
    const float4* base = reinterpret_cast<const float4*>(in + (size_t)bg * 131072);
    float s = 0.f, q = 0.f;
    for (int i = t; i < 32768; i += 256) {
        float4 v = base[i];
        s += (v.x + v.y) + (v.z + v.w);
        q += (v.x * v.x + v.y * v.y) + (v.z * v.z + v.w * v.w);
    }
    __shared__ float rs[256];
    __shared__ float rq[256];
    rs[t] = s; rq[t] = q;
    __syncthreads();
    for (int off = 128; off > 0; off >>= 1) {
        if (t < off) { rs[t] += rs[t + off]; rq[t] += rq[t + off]; }
        __syncthreads();
    }
    if (t == 0) {
        float mean = rs[0] * (1.f / 131072.f);
        float var  = rq[0] * (1.f / 131072.f) - mean * mean;
        g_mean[bg] = mean;
        g_rstd[bg] = rsqrtf(var + 1e-6f);
    }
}

// ---------------------------------------------------------------------------
// Dual GEMM: [Wa; Wb] (128x64) @ gn1 (64x128pix tile) with groupnorm+relu
// fused into the A(tile)-load and the V' epilogue (+b1 - r*w_p0).
// Grid: 2048 CTAs x 256 threads. Thread tile: 8 outputs x 8 pixels.
// ---------------------------------------------------------------------------
__global__ __launch_bounds__(256) void gemm_uv_kernel(
    const float* __restrict__ xin, const float* __restrict__ r,
    const float* __restrict__ w1, const float* __restrict__ b1,
    const float* __restrict__ gnw, const float* __restrict__ gnb)
{
    extern __shared__ float sm[];
    float* sW = sm;            // [64][128] k-major: sW[k*128+m]
    float* sX = sm + 8192;     // [64][128] gn1 tile: sX[k*128+j]
    float* sR = sm + 16384;    // [128] center r

    int t  = threadIdx.x;
    int p0 = blockIdx.x << 7;         // global pixel base (tile of 128)
    int b  = p0 >> 16;
    int pl = p0 & 65535;
    int bgBase = b << 5;

    // weights: m<64 -> Wa row m (cols 0..63 of w1), m>=64 -> Wb row m-64 (cols 64..127)
    for (int e = t; e < 8192; e += 256) {
        int k = e >> 7, m = e & 127;
        float v = (m < 64) ? w1[m * 131 + k] : w1[(m - 64) * 131 + 64 + k];
        sW[k * 128 + m] = v;
    }
    // input tile with fused groupnorm + relu
    for (int e = t; e < 8192; e += 256) {
        int k = e >> 7, j = e & 127;
        int grp = bgBase + (k >> 1);
        float sc = g_rstd[grp] * gnw[k];
        float bi = gnb[k] - g_mean[grp] * sc;
        float v  = xin[((size_t)(b * 64 + k) << 16) + pl + j];
        sX[k * 128 + j] = fmaxf(fmaf(v, sc, bi), 0.f);
    }
    if (t < 128) sR[t] = r[((size_t)b << 16) + pl + t];
    __syncthreads();

    int ty = t >> 4, tx = t & 15;
    float acc[8][8];
#pragma unroll
    for (int i = 0; i < 8; i++)
#pragma unroll
        for (int j = 0; j < 8; j++) acc[i][j] = 0.f;

#pragma unroll 8
    for (int k = 0; k < 64; k++) {
        const float* wr = sW + k * 128 + ty * 8;
        float4 a0 = *reinterpret_cast<const float4*>(wr);
        float4 a1 = *reinterpret_cast<const float4*>(wr + 4);
        const float* xr = sX + k * 128;
        float4 c0 = *reinterpret_cast<const float4*>(xr + tx * 4);
        float4 c1 = *reinterpret_cast<const float4*>(xr + 64 + tx * 4);
        float av[8] = {a0.x, a0.y, a0.z, a0.w, a1.x, a1.y, a1.z, a1.w};
        float bv[8] = {c0.x, c0.y, c0.z, c0.w, c1.x, c1.y, c1.z, c1.w};
#pragma unroll
        for (int i = 0; i < 8; i++)
#pragma unroll
            for (int j = 0; j < 8; j++)
                acc[i][j] = fmaf(av[i], bv[j], acc[i][j]);
    }

#pragma unroll
    for (int i = 0; i < 8; i++) {
        int m = ty * 8 + i;
        if (m < 64) {
            float* dst = g_U + (size_t)m * NPIX + p0;
            float4 v0 = make_float4(acc[i][0], acc[i][1], acc[i][2], acc[i][3]);
            float4 v1 = make_float4(acc[i][4], acc[i][5], acc[i][6], acc[i][7]);
            *reinterpret_cast<float4*>(dst + tx * 4) = v0;
            *reinterpret_cast<float4*>(dst + 64 + tx * 4) = v1;
        } else {
            int o = m - 64;
            float bb  = b1[o];
            float wp0 = w1[o * 131 + 128];
            float* dst = g_V + (size_t)o * NPIX + p0;
            float4 v0, v1;
            v0.x = acc[i][0] + bb - sR[tx * 4 + 0] * wp0;
            v0.y = acc[i][1] + bb - sR[tx * 4 + 1] * wp0;
            v0.z = acc[i][2] + bb - sR[tx * 4 + 2] * wp0;
            v0.w = acc[i][3] + bb - sR[tx * 4 + 3] * wp0;
            v1.x = acc[i][4] + bb - sR[64 + tx * 4 + 0] * wp0;
            v1.y = acc[i][5] + bb - sR[64 + tx * 4 + 1] * wp0;
            v1.z = acc[i][6] + bb - sR[64 + tx * 4 + 2] * wp0;
            v1.w = acc[i][7] + bb - sR[64 + tx * 4 + 3] * wp0;
            *reinterpret_cast<float4*>(dst + tx * 4) = v0;
            *reinterpret_cast<float4*>(dst + 64 + tx * 4) = v1;
        }
    }
}

// ---------------------------------------------------------------------------
// Edge-max: per 128-pixel tile loop 9 shifts, build t_s = relu(U_shift + V' +
// r_s*q_s) in smem, GEMM with w2 (64x64), running elementwise max, epilogue
// +b2 (+x residual if add_res). Shift wraps use &63 / &1023.
// ---------------------------------------------------------------------------
__global__ __launch_bounds__(256) void edge_max_kernel(
    const float* __restrict__ r, const float* __restrict__ w1,
    const float* __restrict__ w2, const float* __restrict__ b2,
    const float* __restrict__ xres, float* __restrict__ out, int add_res)
{
    extern __shared__ float sm[];
    float* sW2 = sm;             // 4096: [64][64] k-major
    float* sV  = sm + 4096;      // 8192
    float* sB  = sm + 12288;     // 8192
    float* sQ  = sm + 20480;     // 576: q vectors per shift
    float* sRs = sm + 21056;     // 128: shifted r
    float* sB2 = sm + 21184;     // 64

    int t  = threadIdx.x;
    int p0 = blockIdx.x << 7;
    int b  = p0 >> 16;
    int pl = p0 & 65535;
    int w0 = pl >> 10;
    int h0 = pl & 1023;

    for (int e = t; e < 4096; e += 256) {
        int o = e >> 6, k = e & 63;
        sW2[k * 64 + o] = w2[e];          // w2[o*64+k]
    }
    for (int e = t; e < 8192; e += 256) {
        int k = e >> 7, j = e & 127;
        sV[e] = g_V[((size_t)k << 18) + p0 + j];
    }
    for (int e = t; e < 576; e += 256) {
        int s = e >> 6, k = e & 63;
        int swv = s / 3 - 1, shv = s % 3 - 1;
        float ca = cosf(swv * AZI_C), sa = sinf(swv * AZI_C);
        float ci = cosf(shv * INC_C), si = sinf(shv * INC_C);
        sQ[e] = ca * ci * w1[k * 131 + 128] + ca * si * w1[k * 131 + 129]
              + sa * w1[k * 131 + 130];
    }
    if (t < 64) sB2[t] = b2[t];
    __syncthreads();

    int ty = t >> 4, tx = t & 15;
    float best[4][8];
#pragma unroll
    for (int i = 0; i < 4; i++)
#pragma unroll
        for (int j = 0; j < 8; j++) best[i][j] = -1e30f;

    for (int s = 0; s < 9; s++) {
        int swv = s / 3 - 1, shv = s % 3 - 1;
        int wsrc = (w0 - swv) & 63;
        size_t rowbase = ((size_t)b << 16) + ((size_t)wsrc << 10);
        if (t < 128) {
            int hs = (h0 + t - shv) & 1023;
            sRs[t] = r[rowbase + hs];
        }
        __syncthreads();
        for (int e = t; e < 8192; e += 256) {
            int k = e >> 7, j = e & 127;
            int hs = (h0 + j - shv) & 1023;
            float u = g_U[((size_t)k << 18) + rowbase + hs];
            sB[e] = fmaxf(fmaf(sRs[j], sQ[s * 64 + k], u + sV[e]), 0.f);
        }
        __syncthreads();

        float acc[4][8];
#pragma unroll
        for (int i = 0; i < 4; i++)
#pragma unroll
            for (int j = 0; j < 8; j++) acc[i][j] = 0.f;

#pragma unroll 8
        for (int k = 0; k < 64; k++) {
            float4 a  = *reinterpret_cast<const float4*>(sW2 + k * 64 + ty * 4);
            const float* br = sB + k * 128;
            float4 c0 = *reinterpret_cast<const float4*>(br + tx * 4);
            float4 c1 = *reinterpret_cast<const float4*>(br + 64 + tx * 4);
            float av[4] = {a.x, a.y, a.z, a.w};
            float bv[8] = {c0.x, c0.y, c0.z, c0.w, c1.x, c1.y, c1.z, c1.w};
#pragma unroll
            for (int i = 0; i < 4; i++)
#pragma unroll
                for (int j = 0; j < 8; j++)
                    acc[i][j] = fmaf(av[i], bv[j], acc[i][j]);
        }
#pragma unroll
        for (int i = 0; i < 4; i++)
#pragma unroll
            for (int j = 0; j < 8; j++)
                best[i][j] = fmaxf(best[i][j], acc[i][j]);
        __syncthreads();
    }

#pragma unroll
    for (int i = 0; i < 4; i++) {
        int o = ty * 4 + i;
        float bias = sB2[o];
        size_t obase = ((size_t)(b * 64 + o) << 16) + pl;
        float4 v0 = make_float4(best[i][0] + bias, best[i][1] + bias,
                                best[i][2] + bias, best[i][3] + bias);
        float4 v1 = make_float4(best[i][4] + bias, best[i][5] + bias,
                                best[i][6] + bias, best[i][7] + bias);
        if (add_res) {
            float4 x0 = *reinterpret_cast<const float4*>(xres + obase + tx * 4);
            float4 x1 = *reinterpret_cast<const float4*>(xres + obase + 64 + tx * 4);
            v0.x += x0.x; v0.y += x0.y; v0.z += x0.z; v0.w += x0.w;
            v1.x += x1.x; v1.y += x1.y; v1.z += x1.z; v1.w += x1.w;
        }
        *reinterpret_cast<float4*>(out + obase + tx * 4) = v0;
        *reinterpret_cast<float4*>(out + obase + 64 + tx * 4) = v1;
    }
}

// ---------------------------------------------------------------------------
extern "C" void kernel_launch(void* const* d_in, const int* in_sizes, int n_in,
                              void* d_out, int out_size) {
    const float* x     = (const float*)d_in[0];
    const float* r     = (const float*)d_in[1];
    const float* n1_w  = (const float*)d_in[2];
    const float* n1_b  = (const float*)d_in[3];
    const float* c1_w1 = (const float*)d_in[4];
    const float* c1_b1 = (const float*)d_in[5];
    const float* c1_w2 = (const float*)d_in[6];
    const float* c1_b2 = (const float*)d_in[7];
    const float* n2_w  = (const float*)d_in[8];
    const float* n2_b  = (const float*)d_in[9];
    const float* c2_w1 = (const float*)d_in[10];
    const float* c2_b1 = (const float*)d_in[11];
    const float* c2_w2 = (const float*)d_in[12];
    const float* c2_b2 = (const float*)d_in[13];
    float* out = (float*)d_out;

    const int GEMM_SMEM = 16512 * 4;   // 66048 B
    const int EDGE_SMEM = 21248 * 4;   // 84992 B
    cudaFuncSetAttribute(gemm_uv_kernel,
                         cudaFuncAttributeMaxDynamicSharedMemorySize, GEMM_SMEM);
    cudaFuncSetAttribute(edge_max_kernel,
                         cudaFuncAttributeMaxDynamicSharedMemorySize, EDGE_SMEM);

    // Block 1
    gn_stats_kernel<<<128, 256>>>(x);
    gemm_uv_kernel<<<2048, 256, GEMM_SMEM>>>(x, r, c1_w1, c1_b1, n1_w, n1_b);
    edge_max_kernel<<<2048, 256, EDGE_SMEM>>>(r, c1_w1, c1_w2, c1_b2,
                                              nullptr, out, 0);   // h1 -> d_out (scratch)
    // Block 2
    gn_stats_kernel<<<128, 256>>>(out);
    gemm_uv_kernel<<<2048, 256, GEMM_SMEM>>>(out, r, c2_w1, c2_b1, n2_w, n2_b);
    edge_max_kernel<<<2048, 256, EDGE_SMEM>>>(r, c2_w1, c2_w2, c2_b2,
                                              x, out, 1);         // out = x + h2
}